// round 13
// baseline (speedup 1.0000x reference)
#include <cuda_runtime.h>
#include <cuda_fp16.h>
#include <cstdint>

// LightGCN bipartite message passing, grouped-scatter + fp16-gather formulation.
//   agg_items[i] = sum_{e: i_idx[e]==i} norm_e * user_emb[u_idx[e]]
//   agg_users[u] = sum_{e: u_idx[e]==u} norm_e * item_emb[i_idx[e]]
// Output = [agg_users (100000x64) | agg_items (50000x64)], f32.
//
// Pipeline (3 launches, graph-capturable, no allocation):
//   1. convert_kernel — f32 embeddings -> fp16 scratch tables; zero counters
//   2. scatter_kernel — bin each edge's {src, norm_f32} into its destination's
//                       fixed-capacity payload row (4 edges/thread, vector loads)
//   3. agg_kernel     — unified both-sides: one warp per segment, 2 edges/warp-
//                       iteration, fp16 gather + f32 accumulate, single store.
//                       Capacity overflow (astronomically rare) handled inline.

#define NUM_USERS 100000
#define NUM_ITEMS 50000
#define DIM       64
#define CAP_I     144     // Poisson(80):  P(bin>144) ~ 1e-9
#define CAP_U     88      // Poisson(40):  P(bin>88)  ~ 5e-10
#define OVF_CAP   16384

// Static scratch (no allocation anywhere).
__device__ int2   d_item_pay[(size_t)NUM_ITEMS * CAP_I];   // {u, norm_bits}  57.6MB
__device__ int2   d_user_pay[(size_t)NUM_USERS * CAP_U];   // {i, norm_bits}  70.4MB
__device__ int    d_item_cnt[NUM_ITEMS];
__device__ int    d_user_cnt[NUM_USERS];
__device__ int4   d_ovf[OVF_CAP];                          // {dest, src, norm_bits, side}
__device__ int    d_ovf_cnt;
__device__ __half d_user_h[(size_t)NUM_USERS * DIM];       // 12.8MB
__device__ __half d_item_h[(size_t)NUM_ITEMS * DIM];       //  6.4MB

// ---------------------------------------------------------------- convert+zero
__global__ void __launch_bounds__(256)
convert_kernel(const float2* __restrict__ user_emb,
               const float2* __restrict__ item_emb)
{
    int t = blockIdx.x * blockDim.x + threadIdx.x;

    if (t < NUM_ITEMS) d_item_cnt[t] = 0;
    if (t < NUM_USERS) d_user_cnt[t] = 0;
    if (t == 0)        d_ovf_cnt = 0;

    const int NU2 = NUM_USERS * (DIM / 2);   // float2 elements in user table
    const int NI2 = NUM_ITEMS * (DIM / 2);
    if (t < NU2) {
        float2 f = __ldg(&user_emb[t]);
        ((half2*)d_user_h)[t] = __float22half2_rn(f);
    } else if (t < NU2 + NI2) {
        int k = t - NU2;
        float2 f = __ldg(&item_emb[k]);
        ((half2*)d_item_h)[k] = __float22half2_rn(f);
    }
}

// ---------------------------------------------------------------- scatter
__device__ __forceinline__ void scatter_one(int u, int i, float nf)
{
    int nb = __float_as_int(nf);

    int si = atomicAdd(&d_item_cnt[i], 1);
    if (si < CAP_I) {
        d_item_pay[(unsigned)i * CAP_I + si] = make_int2(u, nb);
    } else {
        int s = atomicAdd(&d_ovf_cnt, 1);
        if (s < OVF_CAP) d_ovf[s] = make_int4(i, u, nb, 0);   // side 0: item dest
    }

    int su = atomicAdd(&d_user_cnt[u], 1);
    if (su < CAP_U) {
        d_user_pay[(unsigned)u * CAP_U + su] = make_int2(i, nb);
    } else {
        int s = atomicAdd(&d_ovf_cnt, 1);
        if (s < OVF_CAP) d_ovf[s] = make_int4(u, i, nb, 1);   // side 1: user dest
    }
}

__global__ void __launch_bounds__(256)
scatter_kernel(const int*   __restrict__ u_idx,
               const int*   __restrict__ i_idx,
               const float* __restrict__ edge_norm,
               int num_edges)
{
    int nquad = num_edges >> 2;
    int t = blockIdx.x * blockDim.x + threadIdx.x;
    if (t < nquad) {
        int4   uu = __ldg(&((const int4*)u_idx)[t]);
        int4   ii = __ldg(&((const int4*)i_idx)[t]);
        float4 nn = __ldg(&((const float4*)edge_norm)[t]);
        scatter_one(uu.x, ii.x, nn.x);
        scatter_one(uu.y, ii.y, nn.y);
        scatter_one(uu.z, ii.z, nn.z);
        scatter_one(uu.w, ii.w, nn.w);
    }
    if (t == 0) {   // ≤3 remainder edges
        for (int e = nquad * 4; e < num_edges; e++)
            scatter_one(__ldg(&u_idx[e]), __ldg(&i_idx[e]), __ldg(&edge_norm[e]));
    }
}

// ---------------------------------------------------------------- aggregate
// One warp per segment; 2 edges per iteration (16 lanes x 4 dims each).
// fp16 row gather (128B/edge), f32 accumulate, one float4 store per lane<16.
__global__ void __launch_bounds__(256)
agg_kernel(float4* __restrict__ agg_users4, float4* __restrict__ agg_items4)
{
    int w = (blockIdx.x * blockDim.x + threadIdx.x) >> 5;
    if (w >= NUM_ITEMS + NUM_USERS) return;

    int lane = threadIdx.x & 31;
    int sub  = lane >> 4;        // which of the 2 concurrent edges
    int l    = lane & 15;        // dim chunk (4 dims) within the row

    const int2* pay;  const int* cnts;  const uint2* embh;
    float4* out4;  unsigned cap;  int side, seg;

    if (w < NUM_ITEMS) {
        seg = w;               pay = d_item_pay;  cnts = d_item_cnt;
        embh = (const uint2*)d_user_h;  out4 = agg_items4;  cap = CAP_I;  side = 0;
    } else {
        seg = w - NUM_ITEMS;   pay = d_user_pay;  cnts = d_user_cnt;
        embh = (const uint2*)d_item_h;  out4 = agg_users4;  cap = CAP_U;  side = 1;
    }

    int raw = cnts[seg];
    int cnt = min(raw, (int)cap);
    unsigned base = (unsigned)seg * cap;

    float4 acc = make_float4(0.f, 0.f, 0.f, 0.f);

    // software-pipelined payload: load pair e+2 while gathering pair e
    int2 p = (sub < cnt) ? __ldg(&pay[base + sub]) : make_int2(0, 0);
    for (int e = 0; e < cnt; e += 2) {
        int ni = e + 2 + sub;
        int2 pn = (ni < cnt) ? __ldg(&pay[base + ni]) : make_int2(0, 0);

        float n  = __int_as_float(p.y);                         // 0 for inactive lane
        uint2 hv = __ldg(&embh[((unsigned)p.x << 4) + l]);      // 8B = 4 halfs
        float2 f0 = __half22float2(*(const half2*)&hv.x);
        float2 f1 = __half22float2(*(const half2*)&hv.y);
        acc.x = fmaf(n, f0.x, acc.x);
        acc.y = fmaf(n, f0.y, acc.y);
        acc.z = fmaf(n, f1.x, acc.z);
        acc.w = fmaf(n, f1.y, acc.w);
        p = pn;
    }

    // capacity overflow: normally never taken
    if (raw > (int)cap) {
        int novf = d_ovf_cnt;
        if (novf > OVF_CAP) novf = OVF_CAP;
        for (int k = 0; k < novf; k++) {
            int4 o = d_ovf[k];
            if (o.w == side && o.x == seg && sub == 0) {
                float nn = __int_as_float(o.z);
                uint2 hv = __ldg(&embh[((unsigned)o.y << 4) + l]);
                float2 f0 = __half22float2(*(const half2*)&hv.x);
                float2 f1 = __half22float2(*(const half2*)&hv.y);
                acc.x = fmaf(nn, f0.x, acc.x);
                acc.y = fmaf(nn, f0.y, acc.y);
                acc.z = fmaf(nn, f1.x, acc.z);
                acc.w = fmaf(nn, f1.y, acc.w);
            }
        }
    }

    // combine the two edge-halves, store once (covers 0xAA poison)
    acc.x += __shfl_down_sync(0xffffffffu, acc.x, 16);
    acc.y += __shfl_down_sync(0xffffffffu, acc.y, 16);
    acc.z += __shfl_down_sync(0xffffffffu, acc.z, 16);
    acc.w += __shfl_down_sync(0xffffffffu, acc.w, 16);
    if (sub == 0)
        out4[(unsigned)seg * (DIM / 4) + l] = acc;
}

// ---------------------------------------------------------------- launch
extern "C" void kernel_launch(void* const* d_in, const int* in_sizes, int n_in,
                              void* d_out, int out_size)
{
    const float* user_emb  = (const float*)d_in[0];
    const float* item_emb  = (const float*)d_in[1];
    const float* edge_norm = (const float*)d_in[2];
    const int*   u_idx     = (const int*)d_in[3];
    const int*   i_idx     = (const int*)d_in[4];

    int num_edges = in_sizes[2];   // 4,000,000

    float4* agg_users4 = (float4*)d_out;
    float4* agg_items4 = agg_users4 + (size_t)NUM_USERS * (DIM / 4);

    // 1. convert to fp16 + zero counters
    int conv_threads = (NUM_USERS + NUM_ITEMS) * (DIM / 2);   // 4.8M
    convert_kernel<<<(conv_threads + 255) / 256, 256>>>(
        (const float2*)user_emb, (const float2*)item_emb);

    // 2. scatter edges into destination bins (4 edges per thread)
    int nthreads = (num_edges + 3) / 4;
    scatter_kernel<<<(nthreads + 255) / 256, 256>>>(u_idx, i_idx, edge_norm, num_edges);

    // 3. aggregate both sides (one warp per segment)
    int warps = NUM_ITEMS + NUM_USERS;             // 150,000
    agg_kernel<<<(warps * 32 + 255) / 256, 256>>>(agg_users4, agg_items4);
}